// round 14
// baseline (speedup 1.0000x reference)
#include <cuda_runtime.h>
#include <cuda_fp16.h>
#include <math.h>
#include <stdint.h>

#define BATCH 512
#define NTOK 65
#define EDIM 384
#define HEADS 6
#define DHD 64
#define DEPTH 12
#define MLPDIM 1536
#define NCLS 1000
#define TOPK 16
#define INNERD 384
#define PDIM 768
#define NPATCH 64
#define ROWS (BATCH*NTOK)     /* 33280 = 260*128 */
#define PROWS (BATCH*NPATCH)  /* 32768 = 256*128 */

// ---------------- scratch ----------------
__device__ float g_x[ROWS*EDIM];
__device__ float g_ln[ROWS*EDIM];
__device__ float g_mlp[ROWS*MLPDIM];   // mlp hidden; also patch vectors [32768,768]
__device__ float g_qkv[ROWS*3*INNERD];
__device__ float g_o[ROWS*EDIM];
__device__ float g_bias[DEPTH*NTOK*NTOK];

// transposed + fp16-split weights [Nc][K]
#define OFF_PE  0
#define SZ_PE   (384*768)
#define OFF_QKV (SZ_PE)
#define SZ_QKV  (1152*384)
#define OFF_OUT (OFF_QKV + 12*SZ_QKV)
#define SZ_OUT  (384*384)
#define OFF_FF1 (OFF_OUT + 12*SZ_OUT)
#define SZ_FF1  (1536*384)
#define OFF_FF2 (OFF_FF1 + 12*SZ_FF1)
#define SZ_FF2  (384*1536)
#define WT_TOT  (OFF_FF2 + 12*SZ_FF2)
__device__ __half g_wb[WT_TOT];
__device__ __half g_ws[WT_TOT];

// ---------------- helpers ----------------
__device__ __forceinline__ float2 block_reduce2(float s, float s2, float* red) {
    int lane = threadIdx.x & 31, warp = threadIdx.x >> 5;
    #pragma unroll
    for (int o = 16; o; o >>= 1) {
        s  += __shfl_down_sync(0xffffffffu, s,  o);
        s2 += __shfl_down_sync(0xffffffffu, s2, o);
    }
    __syncthreads();
    if (lane == 0) { red[warp] = s; red[32 + warp] = s2; }
    __syncthreads();
    int nw = blockDim.x >> 5;
    if (warp == 0) {
        s  = (lane < nw) ? red[lane] : 0.f;
        s2 = (lane < nw) ? red[32 + lane] : 0.f;
        #pragma unroll
        for (int o = 16; o; o >>= 1) {
            s  += __shfl_down_sync(0xffffffffu, s,  o);
            s2 += __shfl_down_sync(0xffffffffu, s2, o);
        }
        if (lane == 0) { red[0] = s; red[1] = s2; }
    }
    __syncthreads();
    return make_float2(red[0], red[1]);
}

__device__ __forceinline__ unsigned f2tf(float x) {
    unsigned u;
    asm("cvt.rna.tf32.f32 %0, %1;" : "=r"(u) : "f"(x));
    return u;
}
__device__ __forceinline__ void tfsplit(float x, unsigned& ub, unsigned& us) {
    ub = f2tf(x);
    us = f2tf(x - __uint_as_float(ub));
}
__device__ __forceinline__ void hsplit(float x, __half& h1, __half& h2) {
    h1 = __float2half_rn(x);
    h2 = __float2half_rn(x - __half2float(h1));
}
__device__ __forceinline__ uint32_t smem_u32(const void* p) {
    uint32_t a;
    asm("{ .reg .u64 t; cvta.to.shared.u64 t, %1; cvt.u32.u64 %0, t; }" : "=r"(a) : "l"(p));
    return a;
}
__device__ __forceinline__ void ldm4(unsigned* r, uint32_t addr) {
    asm volatile("ldmatrix.sync.aligned.m8n8.x4.shared.b16 {%0,%1,%2,%3}, [%4];"
        : "=r"(r[0]), "=r"(r[1]), "=r"(r[2]), "=r"(r[3]) : "r"(addr));
}
__device__ __forceinline__ void cpa16(uint32_t dst, const void* src) {
    asm volatile("cp.async.cg.shared.global [%0], [%1], 16;" :: "r"(dst), "l"(src) : "memory");
}
#define CP_COMMIT() asm volatile("cp.async.commit_group;" ::: "memory")
#define CP_WAIT0()  asm volatile("cp.async.wait_group 0;" ::: "memory")

#define MMA16(d, a, b0, b1) \
    asm volatile("mma.sync.aligned.m16n8k16.row.col.f32.f16.f16.f32 " \
        "{%0,%1,%2,%3}, {%4,%5,%6,%7}, {%8,%9}, {%0,%1,%2,%3};" \
        : "+f"((d)[0]), "+f"((d)[1]), "+f"((d)[2]), "+f"((d)[3]) \
        : "r"((a)[0]), "r"((a)[1]), "r"((a)[2]), "r"((a)[3]), "r"(b0), "r"(b1))

// ---------------- bias expansion ----------------
__global__ void bias_kernel(const float* __restrict__ tables, float* __restrict__ biasout) {
    int l = blockIdx.x;
    for (int e = threadIdx.x; e < NTOK*NTOK; e += blockDim.x) {
        int i = e / NTOK, j = e % NTOK;
        float v = 0.f;
        if (i > 0 && j > 0) {
            int pi = i - 1, pj = j - 1;
            int r1 = pi >> 3, c1 = pi & 7, r2 = pj >> 3, c2 = pj & 7;
            int idx = (r1 - r2 + 7) * 15 + (c1 - c2 + 7);
            v = tables[l * 225 + idx];
        }
        biasout[l * NTOK * NTOK + e] = v;
    }
}

// ---------------- weight transpose + fp16 split: dst[n][k] = src[k][n] ----------------
__global__ __launch_bounds__(256) void tsplit_kernel(const float* __restrict__ src,
        __half* __restrict__ db, __half* __restrict__ ds, int K, int N,
        long srcStride, long dstStride) {
    __shared__ float t[32][33];
    int l = blockIdx.z;
    src += (size_t)l * srcStride;
    db  += (size_t)l * dstStride;
    ds  += (size_t)l * dstStride;
    int n0 = blockIdx.x * 32, k0 = blockIdx.y * 32;
    int tx = threadIdx.x & 31, ty = threadIdx.x >> 5;
    for (int i = ty; i < 32; i += 8)
        t[i][tx] = src[(size_t)(k0 + i) * N + n0 + tx];
    __syncthreads();
    for (int i = ty; i < 32; i += 8) {
        float v = t[tx][i];
        __half h1, h2; hsplit(v, h1, h2);
        size_t o = (size_t)(n0 + i) * K + k0 + tx;
        db[o] = h1; ds[o] = h2;
    }
}

// ---------------- patch gather + LN(768) ----------------
__global__ __launch_bounds__(256) void patch_kernel(const float* __restrict__ img,
        const float* __restrict__ w, const float* __restrict__ b, float* __restrict__ pe) {
    __shared__ float pv[PDIM];
    __shared__ float red[64];
    int bp = blockIdx.x;
    int bb = bp >> 6, p = bp & 63;
    int hp = p >> 3, wp = p & 7;
    int tid = threadIdx.x;
    for (int u = tid; u < PDIM; u += 256) {
        int c = u >> 8, rr = u & 255, p1 = rr >> 4, p2 = rr & 15;
        float v = img[((size_t)(bb * 3 + c) * 128 + hp * 16 + p1) * 128 + wp * 16 + p2];
        pv[(p1 * 16 + p2) * 3 + c] = v;
    }
    __syncthreads();
    float s = 0.f, s2 = 0.f;
    for (int u = tid; u < PDIM; u += 256) { float v = pv[u]; s += v; s2 += v * v; }
    float2 r = block_reduce2(s, s2, red);
    float mu = r.x * (1.f / PDIM);
    float var = r.y * (1.f / PDIM) - mu * mu;
    float rs = rsqrtf(var + 1e-5f);
    float* out = pe + (size_t)bp * PDIM;
    for (int u = tid; u < PDIM; u += 256)
        out[u] = (pv[u] - mu) * rs * w[u] + b[u];
}

// ---------------- LN(384) ----------------
__global__ __launch_bounds__(128) void ln_kernel(const float* __restrict__ x, int xstride,
        const float* __restrict__ w, const float* __restrict__ b,
        float* __restrict__ y, int ystride) {
    __shared__ float red[64];
    int row = blockIdx.x, tid = threadIdx.x;
    const float* xr = x + (size_t)row * xstride;
    float vals[3];
    float s = 0.f, s2 = 0.f;
    #pragma unroll
    for (int u = 0; u < 3; u++) { float v = xr[tid + u * 128]; vals[u] = v; s += v; s2 += v * v; }
    float2 r = block_reduce2(s, s2, red);
    float mu = r.x * (1.f / EDIM);
    float var = r.y * (1.f / EDIM) - mu * mu;
    float rs = rsqrtf(var + 1e-5f);
    float* yr = y + (size_t)row * ystride;
    #pragma unroll
    for (int u = 0; u < 3; u++) {
        int j = tid + u * 128;
        yr[j] = (vals[u] - mu) * rs * w[j] + b[j];
    }
}

// ---------------- LN(384) + pos emb scatter ----------------
__global__ __launch_bounds__(128) void ln_pos_kernel(const float* __restrict__ y,
        const float* __restrict__ w, const float* __restrict__ b,
        const float* __restrict__ pos, float* __restrict__ x) {
    __shared__ float red[64];
    int rrow = blockIdx.x;
    int bb = rrow >> 6, p = rrow & 63;
    int tid = threadIdx.x;
    const float* xr = y + (size_t)rrow * EDIM;
    float vals[3];
    float s = 0.f, s2 = 0.f;
    #pragma unroll
    for (int u = 0; u < 3; u++) { float v = xr[tid + u * 128]; vals[u] = v; s += v; s2 += v * v; }
    float2 r = block_reduce2(s, s2, red);
    float mu = r.x * (1.f / EDIM);
    float var = r.y * (1.f / EDIM) - mu * mu;
    float rs = rsqrtf(var + 1e-5f);
    float* outr = x + ((size_t)bb * NTOK + 1 + p) * EDIM;
    const float* posr = pos + (size_t)(1 + p) * EDIM;
    #pragma unroll
    for (int u = 0; u < 3; u++) {
        int j = tid + u * 128;
        outr[j] = (vals[u] - mu) * rs * w[j] + b[j] + posr[j];
    }
}

__global__ void cls_kernel(const float* __restrict__ cls, const float* __restrict__ pos,
                           float* __restrict__ x) {
    int b = blockIdx.x, t = threadIdx.x;
    x[(size_t)b * NTOK * EDIM + t] = cls[t] + pos[t];
}

// ================= fp16x2 3-term tensor-core GEMM, A direct-from-global (R8 config) =================
#define LDH 40                 /* halves per B smem row (80B, conflict-free) */
#define HPLANE_B (128*LDH*2)   /* 10240 bytes per plane */
#define STAGE_B (2*HPLANE_B)   /* Bb,Bs = 20480 bytes */
#define H2_SMEM (2*STAGE_B)    /* 40960 bytes */

__global__ __launch_bounds__(256, 2) void gemm_h2_kernel(
        const float* __restrict__ A,
        const __half* __restrict__ Wb, const __half* __restrict__ Ws,
        const float* __restrict__ bias, const float* __restrict__ R,
        float* __restrict__ C, int M, int Nc, int K, int mode) {
    extern __shared__ char smc[];
    uint32_t smb = smem_u32(smc);
    int tid = threadIdx.x;
    int warp = tid >> 5, lane = tid & 31;
    int row0 = blockIdx.y * 128, col0 = blockIdx.x * 128;
    int wm = (warp & 3) * 32;
    int wn = (warp >> 2) * 64;
    int g = lane >> 2, t = lane & 3;
    int lr = lane & 7, quad = lane >> 3;
    int rowl = lr + ((quad & 1) << 3);
    int kadd = (quad >> 1) << 3;

    float acc[2][8][4];
    #pragma unroll
    for (int i = 0; i < 2; i++)
        #pragma unroll
        for (int j = 0; j < 8; j++)
            #pragma unroll
            for (int q = 0; q < 4; q++) acc[i][j][q] = 0.f;

    const float* Ar[2];
    Ar[0] = A + (size_t)(row0 + wm + g) * K + 2 * t;
    Ar[1] = Ar[0] + (size_t)16 * K;

    int srow = tid >> 1;
    int soff = (tid & 1) << 4;
    const int nchunk = K / 32;

    float2 pf[8];
    unsigned aH[2][4], aL[2][4];

    #define FILL_B(s, kg) do { \
        uint32_t dstb = smb + (uint32_t)(s) * STAGE_B + (uint32_t)(srow*LDH + soff)*2; \
        uint32_t dsts = dstb + HPLANE_B; \
        const __half* sb = Wb + (size_t)(col0 + srow) * K + (kg) + soff; \
        const __half* ss = Ws + (size_t)(col0 + srow) * K + (kg) + soff; \
        cpa16(dstb, sb); cpa16(dstb + 16, sb + 8); \
        cpa16(dsts, ss); cpa16(dsts + 16, ss + 8); \
        CP_COMMIT(); \
    } while (0)
    #define PF_LOAD(kb) do { \
        _Pragma("unroll") \
        for (int mt = 0; mt < 2; mt++) { \
            const float* p = Ar[mt] + (kb); \
            pf[mt*4+0] = *(const float2*)(p); \
            pf[mt*4+1] = *(const float2*)(p + (size_t)8 * K); \
            pf[mt*4+2] = *(const float2*)(p + 8); \
            pf[mt*4+3] = *(const float2*)(p + (size_t)8 * K + 8); \
        } \
    } while (0)
    #define CVT_PF() do { \
        _Pragma("unroll") \
        for (int mt = 0; mt < 2; mt++) \
            _Pragma("unroll") \
            for (int j = 0; j < 4; j++) { \
                float2 v = pf[mt*4+j]; \
                __half2 h = __float22half2_rn(v); \
                float2 hr = __half22float2(h); \
                __half2 l = __float22half2_rn(make_float2(v.x - hr.x, v.y - hr.y)); \
                aH[mt][j] = *(unsigned*)&h; \
                aL[mt][j] = *(unsigned*)&l; \
            } \
    } while (0)

    FILL_B(0, 0);
    PF_LOAD(0);
    CP_WAIT0();
    __syncthreads();

    for (int c = 0; c < nchunk; c++) {
        int cur = c & 1;
        if (c + 1 < nchunk) FILL_B(cur ^ 1, (c + 1) * 32);
        uint32_t Bb = smb + (uint32_t)cur * STAGE_B;
        uint32_t Bs = Bb + HPLANE_B;
        #pragma unroll
        for (int ks = 0; ks < 2; ks++) {
            CVT_PF();
            if (ks == 0)      PF_LOAD(c * 32 + 16);
            else if (c + 1 < nchunk) PF_LOAD((c + 1) * 32);
            int kh = ks * 16 + kadd;
            #pragma unroll
            for (int ntp = 0; ntp < 4; ntp++) {
                unsigned bH[4], bL[4];
                uint32_t off = (uint32_t)((wn + ntp * 16 + rowl) * LDH + kh) * 2;
                ldm4(bH, Bb + off);
                ldm4(bL, Bs + off);
                #pragma unroll
                for (int sub = 0; sub < 2; sub++) {
                    unsigned b0h = bH[sub], b1h = bH[2 + sub];
                    unsigned b0l = bL[sub], b1l = bL[2 + sub];
                    #pragma unroll
                    for (int mt = 0; mt < 2; mt++) {
                        MMA16(acc[mt][ntp * 2 + sub], aL[mt], b0h, b1h);
                        MMA16(acc[mt][ntp * 2 + sub], aH[mt], b0l, b1l);
                        MMA16(acc[mt][ntp * 2 + sub], aH[mt], b0h, b1h);
                    }
                }
            }
        }
        if (c + 1 < nchunk) {
            CP_WAIT0();
            __syncthreads();
        }
    }

    #pragma unroll
    for (int mt = 0; mt < 2; mt++) {
        #pragma unroll
        for (int half = 0; half < 2; half++) {
            int gr = row0 + wm + mt * 16 + g + half * 8;
            #pragma unroll
            for (int nt = 0; nt < 8; nt++) {
                int gc = col0 + wn + nt * 8 + 2 * t;
                float v0 = acc[mt][nt][half * 2 + 0];
                float v1 = acc[mt][nt][half * 2 + 1];
                if (bias) { v0 += bias[gc]; v1 += bias[gc + 1]; }
                if (mode == 1) {
                    const float2 rv = *(const float2*)(R + (size_t)gr * Nc + gc);
                    v0 += rv.x; v1 += rv.y;
                } else if (mode == 2) {
                    v0 = 0.5f * v0 * (1.f + erff(v0 * 0.70710678118654752f));
                    v1 = 0.5f * v1 * (1.f + erff(v1 * 0.70710678118654752f));
                }
                *(float2*)(C + (size_t)gr * Nc + gc) = make_float2(v0, v1);
            }
        }
    }
    #undef FILL_B
    #undef PF_LOAD
    #undef CVT_PF
}

// ---------------- legacy tf32x3 mma.sync GEMM (head only, Nc=1000) ----------------
#define BK 32
#define LDT 136
#define TSZ (BK*LDT)
__global__ __launch_bounds__(256, 1) void gemm_tc_kernel(
        const float* __restrict__ A, const float* __restrict__ W,
        const float* __restrict__ bias, const float* __restrict__ R,
        float* __restrict__ C, int M, int Nc, int K, int mode) {
    extern __shared__ unsigned sm[];
    unsigned* Ab_ = sm;
    unsigned* As_ = sm + 2 * TSZ;
    unsigned* Bb_ = sm + 4 * TSZ;
    unsigned* Bs_ = sm + 6 * TSZ;
    int tid = threadIdx.x;
    int col0 = blockIdx.x * 128;
    int row0 = blockIdx.y * 128;
    int lane = tid & 31;
    int warp = tid >> 5;
    int wm = (warp & 3) * 32;
    int wn = (warp >> 2) * 64;
    int g = lane >> 2;
    int t = lane & 3;
    float acc[2][8][4];
    #pragma unroll
    for (int i = 0; i < 2; i++)
        #pragma unroll
        for (int j = 0; j < 8; j++)
            #pragma unroll
            for (int q = 0; q < 4; q++) acc[i][j][q] = 0.f;
    int arow = tid & 127;
    int akoff = (tid >> 7) * 16;
    int bkrow = tid >> 3;
    int bnoff = (tid & 7) * 4;
    bool full_n = (col0 + 128 <= Nc);
    const int nchunk = K / BK;
    float4 aR[4]; float4 bR[4];
    {
        const float* ap = A + (size_t)(row0 + arow) * K + akoff;
        #pragma unroll
        for (int u = 0; u < 4; u++) aR[u] = *(const float4*)(ap + 4 * u);
        if (full_n) {
            const float* bp = W + (size_t)bkrow * Nc + col0 + bnoff;
            #pragma unroll
            for (int u = 0; u < 4; u++) bR[u] = *(const float4*)(bp + 32 * u);
        } else {
            #pragma unroll
            for (int u = 0; u < 4; u++) {
                float tmp[4];
                #pragma unroll
                for (int q = 0; q < 4; q++) {
                    int gc = col0 + bnoff + 32 * u + q;
                    tmp[q] = (gc < Nc) ? W[(size_t)bkrow * Nc + gc] : 0.f;
                }
                bR[u] = make_float4(tmp[0], tmp[1], tmp[2], tmp[3]);
            }
        }
    }
    {
        unsigned *Ab = Ab_, *As = As_, *Bb = Bb_, *Bs = Bs_;
        #pragma unroll
        for (int u = 0; u < 4; u++) {
            float v[4] = {aR[u].x, aR[u].y, aR[u].z, aR[u].w};
            #pragma unroll
            for (int q = 0; q < 4; q++) {
                unsigned ub, us; tfsplit(v[q], ub, us);
                Ab[(akoff + 4*u + q) * LDT + arow] = ub;
                As[(akoff + 4*u + q) * LDT + arow] = us;
            }
        }
        #pragma unroll
        for (int u = 0; u < 4; u++) {
            float v[4] = {bR[u].x, bR[u].y, bR[u].z, bR[u].w};
            unsigned ub[4], us[4];
            #pragma unroll
            for (int q = 0; q < 4; q++) tfsplit(v[q], ub[q], us[q]);
            *(uint4*)(Bb + bkrow * LDT + bnoff + 32 * u) = make_uint4(ub[0], ub[1], ub[2], ub[3]);
            *(uint4*)(Bs + bkrow * LDT + bnoff + 32 * u) = make_uint4(us[0], us[1], us[2], us[3]);
        }
    }
    __syncthreads();
    for (int c = 0; c < nchunk; c++) {
        int cur = c & 1;
        if (c + 1 < nchunk) {
            int k0g = (c + 1) * BK;
            const float* ap = A + (size_t)(row0 + arow) * K + k0g + akoff;
            #pragma unroll
            for (int u = 0; u < 4; u++) aR[u] = *(const float4*)(ap + 4 * u);
            if (full_n) {
                const float* bp = W + (size_t)(k0g + bkrow) * Nc + col0 + bnoff;
                #pragma unroll
                for (int u = 0; u < 4; u++) bR[u] = *(const float4*)(bp + 32 * u);
            } else {
                #pragma unroll
                for (int u = 0; u < 4; u++) {
                    float tmp[4];
                    #pragma unroll
                    for (int q = 0; q < 4; q++) {
                        int gc = col0 + bnoff + 32 * u + q;
                        tmp[q] = (gc < Nc) ? W[(size_t)(k0g + bkrow) * Nc + gc] : 0.f;
                    }
                    bR[u] = make_float4(tmp[0], tmp[1], tmp[2], tmp[3]);
                }
            }
        }
        {
            const unsigned* Ab = Ab_ + cur * TSZ;
            const unsigned* As = As_ + cur * TSZ;
            const unsigned* Bb = Bb_ + cur * TSZ;
            const unsigned* Bs = Bs_ + cur * TSZ;
            #pragma unroll
            for (int kk = 0; kk < 4; kk++) {
                int k0 = kk * 8;
                unsigned aFb[2][4], aFs[2][4];
                #pragma unroll
                for (int mt = 0; mt < 2; mt++) {
                    int m0 = wm + mt * 16 + g;
                    int i00 = (k0 + t) * LDT + m0;
                    int i01 = (k0 + t + 4) * LDT + m0;
                    aFb[mt][0] = Ab[i00]; aFb[mt][1] = Ab[i00 + 8];
                    aFb[mt][2] = Ab[i01]; aFb[mt][3] = Ab[i01 + 8];
                    aFs[mt][0] = As[i00]; aFs[mt][1] = As[i00 + 8];
                    aFs[mt][2] = As[i01]; aFs[mt][3] = As[i01 + 8];
                }
                #pragma unroll
                for (int nt = 0; nt < 8; nt++) {
                    int n0 = wn + nt * 8 + g;
                    int j0 = (k0 + t) * LDT + n0;
                    int j1 = (k0 + t + 4) * LDT + n0;
                    unsigned b0b = Bb[j0], b1b = Bb[j1];
                    unsigned b0s = Bs[j0], b1s = Bs[j1];
                    #pragma unroll
                    for (int mt = 0; mt < 2; mt++) {
                        asm volatile(
                            "mma.sync.aligned.m16n8k8.row.col.f32.tf32.tf32.f32 "
                            "{%0,%1,%2,%3}, {%4,%5,%6,%7}, {%8,%9}, {%0,%1,%2,%3};"
                            : "+f"(acc[mt][nt][0]), "+f"(acc[mt][nt][1]),
                              "+f"(acc[mt][nt][2]), "+f"(acc[mt][nt][3])
                            : "r"(aFs[mt][0]), "r"(aFs[mt][1]), "r"(aFs[mt][2]), "r"(aFs[mt][3]),
                              "r"(b0b), "r"(b1b));
                        asm volatile(
                            "mma.sync.aligned.m16n8k8.row.col.f32.tf32.tf32.f32 "
                            "{%0,%1,%2,%3}, {%4,%5,%6,%7}, {%8,%9}, {%0,%1,%2,%3};"
                            : "+f"(acc[mt][nt][0]), "+f"(acc[mt][nt][1]),
                              "+f"(acc[mt][nt][2]), "+f"(acc[mt][nt][3])
                            : "r"(aFb[mt][0]), "r"(aFb[mt][1]), "r"(aFb[mt][2]), "r"(aFb[mt][3]),
                              "r"(b0s), "r"(b1s));
                        asm volatile(
                            "mma.sync.aligned.m16n8k8.row.col.f32.tf32.tf32.f32 "
                            "{%0,%1,%2,%3}, {%4,%5,%6,%7}, {%8,%9}, {%0,%1,%2,%3};"
                            : "+f"(acc[mt][nt][0]), "+f"(acc[mt][nt][1]),
                              "+f"(acc[mt][nt][2]), "+f"(acc[mt][nt][3])
                            : "r"(aFb[mt][0]), "r"(aFb[mt][1]), "r"(aFb[mt][2]), "r"(aFb[mt][3]),
                              "r"(b0b), "r"(b1b));
                    }
                }
            }
        }
        if (c + 1 < nchunk) {
            int nxt = (c + 1) & 1;
            unsigned *Ab = Ab_ + nxt * TSZ, *As = As_ + nxt * TSZ;
            unsigned *Bb = Bb_ + nxt * TSZ, *Bs = Bs_ + nxt * TSZ;
            #pragma unroll
            for (int u = 0; u < 4; u++) {
                float v[4] = {aR[u].x, aR[u].y, aR[u].z, aR[u].w};
                #pragma unroll
                for (int q = 0; q < 4; q++) {
                    unsigned ub, us; tfsplit(v[q], ub, us);
                    Ab[(akoff + 4*u + q) * LDT + arow] = ub;
                    As[(akoff + 4*u + q) * LDT + arow] = us;
                }
            }
            #pragma unroll
            for (int u = 0; u < 4; u++) {
                float v[4] = {bR[u].x, bR[u].y, bR[u].z, bR[u].w};
                unsigned ub[4], us[4];
                #pragma unroll
                for (int q = 0; q < 4; q++) tfsplit(v[q], ub[q], us[q]);
                *(uint4*)(Bb + bkrow * LDT + bnoff + 32 * u) = make_uint4(ub[0], ub[1], ub[2], ub[3]);
                *(uint4*)(Bs + bkrow * LDT + bnoff + 32 * u) = make_uint4(us[0], us[1], us[2], us[3]);
            }
            __syncthreads();
        }
    }
    #pragma unroll
    for (int mt = 0; mt < 2; mt++) {
        #pragma unroll
        for (int half = 0; half < 2; half++) {
            int gr = row0 + wm + mt * 16 + g + half * 8;
            #pragma unroll
            for (int nt = 0; nt < 8; nt++) {
                int gc = col0 + wn + nt * 8 + 2 * t;
                if (gc >= Nc) continue;
                float v0 = acc[mt][nt][half * 2 + 0];
                float v1 = acc[mt][nt][half * 2 + 1];
                if (bias) { v0 += bias[gc]; v1 += bias[gc + 1]; }
                if (mode == 1) {
                    const float2 rv = *(const float2*)(R + (size_t)gr * Nc + gc);
                    v0 += rv.x; v1 += rv.y;
                } else if (mode == 2) {
                    v0 = 0.5f * v0 * (1.f + erff(v0 * 0.70710678118654752f));
                    v1 = 0.5f * v1 * (1.f + erff(v1 * 0.70710678118654752f));
                }
                *(float2*)(C + (size_t)gr * Nc + gc) = make_float2(v0, v1);
            }
        }
    }
}

// ---------------- attention: 512 threads/block ----------------
__global__ __launch_bounds__(512) void attn_kernel(const float* __restrict__ qkv,
        const float* __restrict__ biasfull, float* __restrict__ o) {
    extern __shared__ float smf[];
    float* qs = smf;
    float* ks = smf + NTOK * NTOK;
    float* vs = smf + 2 * NTOK * NTOK;
    float* sc = smf + 3 * NTOK * NTOK;
    int bh = blockIdx.x;
    int b = bh / HEADS, hd = bh % HEADS;
    int tid = threadIdx.x;
    const float* base = qkv + (size_t)b * NTOK * (3 * INNERD) + hd * DHD;
    for (int e = tid; e < NTOK * DHD; e += 512) {
        int i = e >> 6, d = e & 63;
        const float* r = base + (size_t)i * (3 * INNERD);
        qs[i * 65 + d] = r[d];
        ks[i * 65 + d] = r[INNERD + d];
        vs[i * 65 + d] = r[2 * INNERD + d];
    }
    __syncthreads();
    for (int t = tid; t < 17 * 17; t += 512) {
        int ti = (t / 17) * 4, tj = (t % 17) * 4;
        float acc[4][4] = {};
        #pragma unroll 8
        for (int kk = 0; kk < DHD; kk++) {
            float a[4], w[4];
            #pragma unroll
            for (int u = 0; u < 4; u++) { int ii = ti + u; if (ii > 64) ii = 64; a[u] = qs[ii * 65 + kk]; }
            #pragma unroll
            for (int u = 0; u < 4; u++) { int jj = tj + u; if (jj > 64) jj = 64; w[u] = ks[jj * 65 + kk]; }
            #pragma unroll
            for (int i = 0; i < 4; i++)
                #pragma unroll
                for (int j = 0; j < 4; j++) acc[i][j] = fmaf(a[i], w[j], acc[i][j]);
        }
        #pragma unroll
        for (int u = 0; u < 4; u++) {
            int ii = ti + u; if (ii > 64) break;
            #pragma unroll
            for (int v = 0; v < 4; v++) {
                int jj = tj + v; if (jj > 64) break;
                sc[ii * 66 + jj] = acc[u][v] * 0.125f + biasfull[ii * NTOK + jj];
            }
        }
    }
    __syncthreads();
    int warp = tid >> 5, lane = tid & 31;
    for (int row = warp; row < NTOK; row += 16) {
        float v0 = sc[row * 66 + lane];
        float v1 = sc[row * 66 + 32 + lane];
        float v2 = (lane == 0) ? sc[row * 66 + 64] : -3.402823466e38f;
        bool a0 = true, a1 = true, a2 = (lane == 0);
        bool s0 = false, s1 = false, s2 = false;
        float rowmax = 0.f;
        for (int it = 0; it < TOPK; it++) {
            float bv = -3.402823466e38f; int bi = 127;
            if (a0)            { bv = v0; bi = lane; }
            if (a1 && v1 > bv) { bv = v1; bi = lane + 32; }
            if (a2 && v2 > bv) { bv = v2; bi = 64; }
            #pragma unroll
            for (int off = 16; off; off >>= 1) {
                float ov = __shfl_down_sync(0xffffffffu, bv, off);
                int   oi = __shfl_down_sync(0xffffffffu, bi, off);
                if (ov > bv || (ov == bv && oi < bi)) { bv = ov; bi = oi; }
            }
            bv = __shfl_sync(0xffffffffu, bv, 0);
            bi = __shfl_sync(0xffffffffu, bi, 0);
            if (it == 0) rowmax = bv;
            if (bi == lane)              { a0 = false; s0 = true; }
            else if (bi == lane + 32)    { a1 = false; s1 = true; }
            else if (bi == 64 && lane==0){ a2 = false; s2 = true; }
        }
        float e0 = s0 ? expf(v0 - rowmax) : 0.f;
        float e1 = s1 ? expf(v1 - rowmax) : 0.f;
        float e2 = s2 ? expf(v2 - rowmax) : 0.f;
        float sum = e0 + e1 + e2;
        #pragma unroll
        for (int off = 16; off; off >>= 1) sum += __shfl_down_sync(0xffffffffu, sum, off);
        sum = __shfl_sync(0xffffffffu, sum, 0);
        float inv = 1.0f / sum;
        sc[row * 66 + lane] = e0 * inv;
        sc[row * 66 + 32 + lane] = e1 * inv;
        if (lane == 0) sc[row * 66 + 64] = e2 * inv;
    }
    __syncthreads();
    for (int t = tid; t < 17 * 16; t += 512) {
        int ti = (t >> 4) << 2, td = (t & 15) << 2;
        float acc[4][4] = {};
        for (int j = 0; j < NTOK; j++) {
            float a[4], w[4];
            #pragma unroll
            for (int u = 0; u < 4; u++) { int ii = ti + u; if (ii > 64) ii = 64; a[u] = sc[ii * 66 + j]; }
            #pragma unroll
            for (int u = 0; u < 4; u++) w[u] = vs[j * 65 + td + u];
            #pragma unroll
            for (int i2 = 0; i2 < 4; i2++)
                #pragma unroll
                for (int j2 = 0; j2 < 4; j2++) acc[i2][j2] = fmaf(a[i2], w[j2], acc[i2][j2]);
        }
        #pragma unroll
        for (int u = 0; u < 4; u++) {
            int ii = ti + u; if (ii > 64) break;
            float* orow = o + ((size_t)b * NTOK + ii) * INNERD + hd * DHD + td;
            #pragma unroll
            for (int v = 0; v < 4; v++) orow[v] = acc[u][v];
        }
    }
}

// ---------------- host orchestration ----------------
extern "C" void kernel_launch(void* const* d_in, const int* in_sizes, int n_in,
                              void* d_out, int out_size) {
    (void)in_sizes; (void)n_in; (void)out_size;
    const float* img       = (const float*)d_in[0];
    const float* pe_ln1_w  = (const float*)d_in[1];
    const float* pe_ln1_b  = (const float*)d_in[2];
    const float* pe_w      = (const float*)d_in[3];
    const float* pe_b      = (const float*)d_in[4];
    const float* pe_ln2_w  = (const float*)d_in[5];
    const float* pe_ln2_b  = (const float*)d_in[6];
    const float* cls_tok   = (const float*)d_in[7];
    const float* pos_emb   = (const float*)d_in[8];
    const float* attn_ln_w = (const float*)d_in[9];
    const float* attn_ln_b = (const float*)d_in[10];
    const float* qkv_w     = (const float*)d_in[11];
    const float* out_w     = (const float*)d_in[12];
    const float* out_b     = (const float*)d_in[13];
    const float* btab      = (const float*)d_in[14];
    const float* ff_ln_w   = (const float*)d_in[15];
    const float* ff_ln_b   = (const float*)d_in[16];
    const float* ff_w1     = (const float*)d_in[17];
    const float* ff_b1     = (const float*)d_in[18];
    const float* ff_w2     = (const float*)d_in[19];
    const float* ff_b2     = (const float*)d_in[20];
    const float* fin_ln_w  = (const float*)d_in[21];
    const float* fin_ln_b  = (const float*)d_in[22];
    const float* head_w    = (const float*)d_in[23];
    const float* head_b    = (const float*)d_in[24];
    float* out = (float*)d_out;

    float *px, *pln, *pmlp, *pqkv, *po, *pbias;
    __half *wb, *ws;
    cudaGetSymbolAddress((void**)&px,   g_x);
    cudaGetSymbolAddress((void**)&pln,  g_ln);
    cudaGetSymbolAddress((void**)&pmlp, g_mlp);
    cudaGetSymbolAddress((void**)&pqkv, g_qkv);
    cudaGetSymbolAddress((void**)&po,   g_o);
    cudaGetSymbolAddress((void**)&pbias,g_bias);
    cudaGetSymbolAddress((void**)&wb,   g_wb);
    cudaGetSymbolAddress((void**)&ws,   g_ws);

    const int ATTN_SMEM = (3 * NTOK * NTOK + NTOK * 66) * 4;
    cudaFuncSetAttribute(attn_kernel, cudaFuncAttributeMaxDynamicSharedMemorySize, ATTN_SMEM);
    const int GEMM_SMEM = 8 * TSZ * 4;
    cudaFuncSetAttribute(gemm_tc_kernel, cudaFuncAttributeMaxDynamicSharedMemorySize, GEMM_SMEM);
    cudaFuncSetAttribute(gemm_h2_kernel, cudaFuncAttributeMaxDynamicSharedMemorySize, H2_SMEM);

    patch_kernel<<<PROWS, 256>>>(img, pe_ln1_w, pe_ln1_b, pmlp);                       // 0
    tsplit_kernel<<<dim3(384/32, 768/32, 1), 256>>>(pe_w, wb + OFF_PE, ws + OFF_PE,    // 1
                                                    768, 384, 0, 0);
    tsplit_kernel<<<dim3(1152/32, 384/32, 12), 256>>>(qkv_w, wb + OFF_QKV, ws + OFF_QKV, // 2
                                                      384, 1152, (long)384*1152, (long)SZ_QKV);
    gemm_h2_kernel<<<dim3(3, PROWS/128), 256, H2_SMEM>>>(                              // 3
        pmlp, wb + OFF_PE, ws + OFF_PE, pe_b, nullptr, pln, PROWS, EDIM, PDIM, 0);
    tsplit_kernel<<<dim3(384/32, 384/32, 12), 256>>>(out_w, wb + OFF_OUT, ws + OFF_OUT, // 4
                                                     384, 384, (long)384*384, (long)SZ_OUT);
    tsplit_kernel<<<dim3(1536/32, 384/32, 12), 256>>>(ff_w1, wb + OFF_FF1, ws + OFF_FF1, // 5
                                                      384, 1536, (long)384*1536, (long)SZ_FF1);
    tsplit_kernel<<<dim3(384/32, 1536/32, 12), 256>>>(ff_w2, wb + OFF_FF2, ws + OFF_FF2, // 6
                                                      1536, 384, (long)1536*384, (long)SZ_FF2);
    bias_kernel<<<DEPTH, 256>>>(btab, pbias);                                          // 7
    ln_pos_kernel<<<PROWS, 128>>>(pln, pe_ln2_w, pe_ln2_b, pos_emb, px);               // 8
    cls_kernel<<<BATCH, EDIM>>>(cls_tok, pos_emb, px);                                 // 9

    for (int l = 0; l < DEPTH; l++) {
        ln_kernel<<<ROWS, 128>>>(px, EDIM, attn_ln_w + l * EDIM, attn_ln_b + l * EDIM, pln, EDIM);
        gemm_h2_kernel<<<dim3(9, ROWS/128), 256, H2_SMEM>>>(
            pln, wb + OFF_QKV + (size_t)l * SZ_QKV, ws + OFF_QKV + (size_t)l * SZ_QKV,
            nullptr, nullptr, pqkv, ROWS, 1152, EDIM, 0);
        attn_kernel<<<BATCH * HEADS, 512, ATTN_SMEM>>>(pqkv, pbias + l * NTOK * NTOK, po);
        gemm_h2_kernel<<<dim3(3, ROWS/128), 256, H2_SMEM>>>(
            po, wb + OFF_OUT + (size_t)l * SZ_OUT, ws + OFF_OUT + (size_t)l * SZ_OUT,
            out_b + l * EDIM, px, px, ROWS, EDIM, EDIM, 1);
        ln_kernel<<<ROWS, 128>>>(px, EDIM, ff_ln_w + l * EDIM, ff_ln_b + l * EDIM, pln, EDIM);
        gemm_h2_kernel<<<dim3(12, ROWS/128), 256, H2_SMEM>>>(
            pln, wb + OFF_FF1 + (size_t)l * SZ_FF1, ws + OFF_FF1 + (size_t)l * SZ_FF1,
            ff_b1 + l * MLPDIM, nullptr, pmlp, ROWS, MLPDIM, EDIM, 2);
        gemm_h2_kernel<<<dim3(3, ROWS/128), 256, H2_SMEM>>>(
            pmlp, wb + OFF_FF2 + (size_t)l * SZ_FF2, ws + OFF_FF2 + (size_t)l * SZ_FF2,
            ff_b2 + l * EDIM, px, px, ROWS, EDIM, MLPDIM, 1);
    }

    ln_kernel<<<BATCH, 128>>>(px, NTOK * EDIM, fin_ln_w, fin_ln_b, pln, EDIM);
    gemm_tc_kernel<<<dim3((NCLS + 127) / 128, BATCH / 128), 256, GEMM_SMEM>>>(
        pln, head_w, head_b, nullptr, out, BATCH, NCLS, EDIM, 0);
}

// round 17
// speedup vs baseline: 1.0254x; 1.0254x over previous
#include <cuda_runtime.h>
#include <cuda_fp16.h>
#include <math.h>
#include <stdint.h>

#define BATCH 512
#define NTOK 65
#define EDIM 384
#define HEADS 6
#define DHD 64
#define DEPTH 12
#define MLPDIM 1536
#define NCLS 1000
#define TOPK 16
#define INNERD 384
#define PDIM 768
#define NPATCH 64
#define ROWS (BATCH*NTOK)     /* 33280 = 260*128 */
#define PROWS (BATCH*NPATCH)  /* 32768 = 256*128 */

// ---------------- scratch ----------------
__device__ float g_x[ROWS*EDIM];
__device__ float g_ln[ROWS*EDIM];
__device__ float g_mlp[ROWS*MLPDIM];   // mlp hidden; also patch vectors [32768,768]
__device__ float g_qkv[ROWS*3*INNERD];
__device__ float g_o[ROWS*EDIM];
__device__ float g_bias[DEPTH*NTOK*NTOK];

// transposed + fp16-split weights [Nc][K]
#define OFF_PE  0
#define SZ_PE   (384*768)
#define OFF_QKV (SZ_PE)
#define SZ_QKV  (1152*384)
#define OFF_OUT (OFF_QKV + 12*SZ_QKV)
#define SZ_OUT  (384*384)
#define OFF_FF1 (OFF_OUT + 12*SZ_OUT)
#define SZ_FF1  (1536*384)
#define OFF_FF2 (OFF_FF1 + 12*SZ_FF1)
#define SZ_FF2  (384*1536)
#define WT_TOT  (OFF_FF2 + 12*SZ_FF2)
__device__ __half g_wb[WT_TOT];
__device__ __half g_ws[WT_TOT];

// ---------------- helpers ----------------
__device__ __forceinline__ float2 block_reduce2(float s, float s2, float* red) {
    int lane = threadIdx.x & 31, warp = threadIdx.x >> 5;
    #pragma unroll
    for (int o = 16; o; o >>= 1) {
        s  += __shfl_down_sync(0xffffffffu, s,  o);
        s2 += __shfl_down_sync(0xffffffffu, s2, o);
    }
    __syncthreads();
    if (lane == 0) { red[warp] = s; red[32 + warp] = s2; }
    __syncthreads();
    int nw = blockDim.x >> 5;
    if (warp == 0) {
        s  = (lane < nw) ? red[lane] : 0.f;
        s2 = (lane < nw) ? red[32 + lane] : 0.f;
        #pragma unroll
        for (int o = 16; o; o >>= 1) {
            s  += __shfl_down_sync(0xffffffffu, s,  o);
            s2 += __shfl_down_sync(0xffffffffu, s2, o);
        }
        if (lane == 0) { red[0] = s; red[1] = s2; }
    }
    __syncthreads();
    return make_float2(red[0], red[1]);
}

__device__ __forceinline__ unsigned f2tf(float x) {
    unsigned u;
    asm("cvt.rna.tf32.f32 %0, %1;" : "=r"(u) : "f"(x));
    return u;
}
__device__ __forceinline__ void tfsplit(float x, unsigned& ub, unsigned& us) {
    ub = f2tf(x);
    us = f2tf(x - __uint_as_float(ub));
}
__device__ __forceinline__ void hsplit(float x, __half& h1, __half& h2) {
    h1 = __float2half_rn(x);
    h2 = __float2half_rn(x - __half2float(h1));
}
__device__ __forceinline__ uint32_t smem_u32(const void* p) {
    uint32_t a;
    asm("{ .reg .u64 t; cvta.to.shared.u64 t, %1; cvt.u32.u64 %0, t; }" : "=r"(a) : "l"(p));
    return a;
}
__device__ __forceinline__ void ldm4(unsigned* r, uint32_t addr) {
    asm volatile("ldmatrix.sync.aligned.m8n8.x4.shared.b16 {%0,%1,%2,%3}, [%4];"
        : "=r"(r[0]), "=r"(r[1]), "=r"(r[2]), "=r"(r[3]) : "r"(addr));
}
__device__ __forceinline__ void cpa16(uint32_t dst, const void* src) {
    asm volatile("cp.async.cg.shared.global [%0], [%1], 16;" :: "r"(dst), "l"(src) : "memory");
}
#define CP_COMMIT() asm volatile("cp.async.commit_group;" ::: "memory")
#define CP_WAIT0()  asm volatile("cp.async.wait_group 0;" ::: "memory")

#define MMA16(d, a, b0, b1) \
    asm volatile("mma.sync.aligned.m16n8k16.row.col.f32.f16.f16.f32 " \
        "{%0,%1,%2,%3}, {%4,%5,%6,%7}, {%8,%9}, {%0,%1,%2,%3};" \
        : "+f"((d)[0]), "+f"((d)[1]), "+f"((d)[2]), "+f"((d)[3]) \
        : "r"((a)[0]), "r"((a)[1]), "r"((a)[2]), "r"((a)[3]), "r"(b0), "r"(b1))

// ---------------- bias expansion ----------------
__global__ void bias_kernel(const float* __restrict__ tables, float* __restrict__ biasout) {
    int l = blockIdx.x;
    for (int e = threadIdx.x; e < NTOK*NTOK; e += blockDim.x) {
        int i = e / NTOK, j = e % NTOK;
        float v = 0.f;
        if (i > 0 && j > 0) {
            int pi = i - 1, pj = j - 1;
            int r1 = pi >> 3, c1 = pi & 7, r2 = pj >> 3, c2 = pj & 7;
            int idx = (r1 - r2 + 7) * 15 + (c1 - c2 + 7);
            v = tables[l * 225 + idx];
        }
        biasout[l * NTOK * NTOK + e] = v;
    }
}

// ---------------- weight transpose + fp16 split: dst[n][k] = src[k][n] ----------------
__global__ __launch_bounds__(256) void tsplit_kernel(const float* __restrict__ src,
        __half* __restrict__ db, __half* __restrict__ ds, int K, int N,
        long srcStride, long dstStride) {
    __shared__ float t[32][33];
    int l = blockIdx.z;
    src += (size_t)l * srcStride;
    db  += (size_t)l * dstStride;
    ds  += (size_t)l * dstStride;
    int n0 = blockIdx.x * 32, k0 = blockIdx.y * 32;
    int tx = threadIdx.x & 31, ty = threadIdx.x >> 5;
    for (int i = ty; i < 32; i += 8)
        t[i][tx] = src[(size_t)(k0 + i) * N + n0 + tx];
    __syncthreads();
    for (int i = ty; i < 32; i += 8) {
        float v = t[tx][i];
        __half h1, h2; hsplit(v, h1, h2);
        size_t o = (size_t)(n0 + i) * K + k0 + tx;
        db[o] = h1; ds[o] = h2;
    }
}

// ---------------- patch gather + LN(768) ----------------
__global__ __launch_bounds__(256) void patch_kernel(const float* __restrict__ img,
        const float* __restrict__ w, const float* __restrict__ b, float* __restrict__ pe) {
    __shared__ float pv[PDIM];
    __shared__ float red[64];
    int bp = blockIdx.x;
    int bb = bp >> 6, p = bp & 63;
    int hp = p >> 3, wp = p & 7;
    int tid = threadIdx.x;
    for (int u = tid; u < PDIM; u += 256) {
        int c = u >> 8, rr = u & 255, p1 = rr >> 4, p2 = rr & 15;
        float v = img[((size_t)(bb * 3 + c) * 128 + hp * 16 + p1) * 128 + wp * 16 + p2];
        pv[(p1 * 16 + p2) * 3 + c] = v;
    }
    __syncthreads();
    float s = 0.f, s2 = 0.f;
    for (int u = tid; u < PDIM; u += 256) { float v = pv[u]; s += v; s2 += v * v; }
    float2 r = block_reduce2(s, s2, red);
    float mu = r.x * (1.f / PDIM);
    float var = r.y * (1.f / PDIM) - mu * mu;
    float rs = rsqrtf(var + 1e-5f);
    float* out = pe + (size_t)bp * PDIM;
    for (int u = tid; u < PDIM; u += 256)
        out[u] = (pv[u] - mu) * rs * w[u] + b[u];
}

// ---------------- LN(384) ----------------
__global__ __launch_bounds__(128) void ln_kernel(const float* __restrict__ x, int xstride,
        const float* __restrict__ w, const float* __restrict__ b,
        float* __restrict__ y, int ystride) {
    __shared__ float red[64];
    int row = blockIdx.x, tid = threadIdx.x;
    const float* xr = x + (size_t)row * xstride;
    float vals[3];
    float s = 0.f, s2 = 0.f;
    #pragma unroll
    for (int u = 0; u < 3; u++) { float v = xr[tid + u * 128]; vals[u] = v; s += v; s2 += v * v; }
    float2 r = block_reduce2(s, s2, red);
    float mu = r.x * (1.f / EDIM);
    float var = r.y * (1.f / EDIM) - mu * mu;
    float rs = rsqrtf(var + 1e-5f);
    float* yr = y + (size_t)row * ystride;
    #pragma unroll
    for (int u = 0; u < 3; u++) {
        int j = tid + u * 128;
        yr[j] = (vals[u] - mu) * rs * w[j] + b[j];
    }
}

// ---------------- LN(384) + pos emb scatter ----------------
__global__ __launch_bounds__(128) void ln_pos_kernel(const float* __restrict__ y,
        const float* __restrict__ w, const float* __restrict__ b,
        const float* __restrict__ pos, float* __restrict__ x) {
    __shared__ float red[64];
    int rrow = blockIdx.x;
    int bb = rrow >> 6, p = rrow & 63;
    int tid = threadIdx.x;
    const float* xr = y + (size_t)rrow * EDIM;
    float vals[3];
    float s = 0.f, s2 = 0.f;
    #pragma unroll
    for (int u = 0; u < 3; u++) { float v = xr[tid + u * 128]; vals[u] = v; s += v; s2 += v * v; }
    float2 r = block_reduce2(s, s2, red);
    float mu = r.x * (1.f / EDIM);
    float var = r.y * (1.f / EDIM) - mu * mu;
    float rs = rsqrtf(var + 1e-5f);
    float* outr = x + ((size_t)bb * NTOK + 1 + p) * EDIM;
    const float* posr = pos + (size_t)(1 + p) * EDIM;
    #pragma unroll
    for (int u = 0; u < 3; u++) {
        int j = tid + u * 128;
        outr[j] = (vals[u] - mu) * rs * w[j] + b[j] + posr[j];
    }
}

__global__ void cls_kernel(const float* __restrict__ cls, const float* __restrict__ pos,
                           float* __restrict__ x) {
    int b = blockIdx.x, t = threadIdx.x;
    x[(size_t)b * NTOK * EDIM + t] = cls[t] + pos[t];
}

// ================= fp16x2 3-term tensor-core GEMM, A direct-from-global (R8 config) =================
#define LDH 40                 /* halves per B smem row (80B, conflict-free) */
#define HPLANE_B (128*LDH*2)   /* 10240 bytes per plane */
#define STAGE_B (2*HPLANE_B)   /* Bb,Bs = 20480 bytes */
#define H2_SMEM (2*STAGE_B)    /* 40960 bytes */

__global__ __launch_bounds__(256, 2) void gemm_h2_kernel(
        const float* __restrict__ A,
        const __half* __restrict__ Wb, const __half* __restrict__ Ws,
        const float* __restrict__ bias, const float* __restrict__ R,
        float* __restrict__ C, int M, int Nc, int K, int mode) {
    extern __shared__ char smc[];
    uint32_t smb = smem_u32(smc);
    int tid = threadIdx.x;
    int warp = tid >> 5, lane = tid & 31;
    int row0 = blockIdx.y * 128, col0 = blockIdx.x * 128;
    int wm = (warp & 3) * 32;
    int wn = (warp >> 2) * 64;
    int g = lane >> 2, t = lane & 3;
    int lr = lane & 7, quad = lane >> 3;
    int rowl = lr + ((quad & 1) << 3);
    int kadd = (quad >> 1) << 3;

    float acc[2][8][4];
    #pragma unroll
    for (int i = 0; i < 2; i++)
        #pragma unroll
        for (int j = 0; j < 8; j++)
            #pragma unroll
            for (int q = 0; q < 4; q++) acc[i][j][q] = 0.f;

    const float* Ar[2];
    Ar[0] = A + (size_t)(row0 + wm + g) * K + 2 * t;
    Ar[1] = Ar[0] + (size_t)16 * K;

    int srow = tid >> 1;
    int soff = (tid & 1) << 4;
    const int nchunk = K / 32;

    float2 pf[8];
    unsigned aH[2][4], aL[2][4];

    #define FILL_B(s, kg) do { \
        uint32_t dstb = smb + (uint32_t)(s) * STAGE_B + (uint32_t)(srow*LDH + soff)*2; \
        uint32_t dsts = dstb + HPLANE_B; \
        const __half* sb = Wb + (size_t)(col0 + srow) * K + (kg) + soff; \
        const __half* ss = Ws + (size_t)(col0 + srow) * K + (kg) + soff; \
        cpa16(dstb, sb); cpa16(dstb + 16, sb + 8); \
        cpa16(dsts, ss); cpa16(dsts + 16, ss + 8); \
        CP_COMMIT(); \
    } while (0)
    #define PF_LOAD(kb) do { \
        _Pragma("unroll") \
        for (int mt = 0; mt < 2; mt++) { \
            const float* p = Ar[mt] + (kb); \
            pf[mt*4+0] = *(const float2*)(p); \
            pf[mt*4+1] = *(const float2*)(p + (size_t)8 * K); \
            pf[mt*4+2] = *(const float2*)(p + 8); \
            pf[mt*4+3] = *(const float2*)(p + (size_t)8 * K + 8); \
        } \
    } while (0)
    #define CVT_PF() do { \
        _Pragma("unroll") \
        for (int mt = 0; mt < 2; mt++) \
            _Pragma("unroll") \
            for (int j = 0; j < 4; j++) { \
                float2 v = pf[mt*4+j]; \
                __half2 h = __float22half2_rn(v); \
                float2 hr = __half22float2(h); \
                __half2 l = __float22half2_rn(make_float2(v.x - hr.x, v.y - hr.y)); \
                aH[mt][j] = *(unsigned*)&h; \
                aL[mt][j] = *(unsigned*)&l; \
            } \
    } while (0)

    FILL_B(0, 0);
    PF_LOAD(0);
    CP_WAIT0();
    __syncthreads();

    for (int c = 0; c < nchunk; c++) {
        int cur = c & 1;
        if (c + 1 < nchunk) FILL_B(cur ^ 1, (c + 1) * 32);
        uint32_t Bb = smb + (uint32_t)cur * STAGE_B;
        uint32_t Bs = Bb + HPLANE_B;
        #pragma unroll
        for (int ks = 0; ks < 2; ks++) {
            CVT_PF();
            if (ks == 0)      PF_LOAD(c * 32 + 16);
            else if (c + 1 < nchunk) PF_LOAD((c + 1) * 32);
            int kh = ks * 16 + kadd;
            #pragma unroll
            for (int ntp = 0; ntp < 4; ntp++) {
                unsigned bH[4], bL[4];
                uint32_t off = (uint32_t)((wn + ntp * 16 + rowl) * LDH + kh) * 2;
                ldm4(bH, Bb + off);
                ldm4(bL, Bs + off);
                #pragma unroll
                for (int sub = 0; sub < 2; sub++) {
                    unsigned b0h = bH[sub], b1h = bH[2 + sub];
                    unsigned b0l = bL[sub], b1l = bL[2 + sub];
                    #pragma unroll
                    for (int mt = 0; mt < 2; mt++) {
                        MMA16(acc[mt][ntp * 2 + sub], aL[mt], b0h, b1h);
                        MMA16(acc[mt][ntp * 2 + sub], aH[mt], b0l, b1l);
                        MMA16(acc[mt][ntp * 2 + sub], aH[mt], b0h, b1h);
                    }
                }
            }
        }
        if (c + 1 < nchunk) {
            CP_WAIT0();
            __syncthreads();
        }
    }

    #pragma unroll
    for (int mt = 0; mt < 2; mt++) {
        #pragma unroll
        for (int half = 0; half < 2; half++) {
            int gr = row0 + wm + mt * 16 + g + half * 8;
            #pragma unroll
            for (int nt = 0; nt < 8; nt++) {
                int gc = col0 + wn + nt * 8 + 2 * t;
                float v0 = acc[mt][nt][half * 2 + 0];
                float v1 = acc[mt][nt][half * 2 + 1];
                if (bias) { v0 += bias[gc]; v1 += bias[gc + 1]; }
                if (mode == 1) {
                    const float2 rv = *(const float2*)(R + (size_t)gr * Nc + gc);
                    v0 += rv.x; v1 += rv.y;
                } else if (mode == 2) {
                    v0 = 0.5f * v0 * (1.f + erff(v0 * 0.70710678118654752f));
                    v1 = 0.5f * v1 * (1.f + erff(v1 * 0.70710678118654752f));
                }
                *(float2*)(C + (size_t)gr * Nc + gc) = make_float2(v0, v1);
            }
        }
    }
    #undef FILL_B
    #undef PF_LOAD
    #undef CVT_PF
}

// ---------------- legacy tf32x3 mma.sync GEMM (head only, Nc=1000) ----------------
#define BK 32
#define LDT 136
#define TSZ (BK*LDT)
__global__ __launch_bounds__(256, 1) void gemm_tc_kernel(
        const float* __restrict__ A, const float* __restrict__ W,
        const float* __restrict__ bias, const float* __restrict__ R,
        float* __restrict__ C, int M, int Nc, int K, int mode) {
    extern __shared__ unsigned sm[];
    unsigned* Ab_ = sm;
    unsigned* As_ = sm + 2 * TSZ;
    unsigned* Bb_ = sm + 4 * TSZ;
    unsigned* Bs_ = sm + 6 * TSZ;
    int tid = threadIdx.x;
    int col0 = blockIdx.x * 128;
    int row0 = blockIdx.y * 128;
    int lane = tid & 31;
    int warp = tid >> 5;
    int wm = (warp & 3) * 32;
    int wn = (warp >> 2) * 64;
    int g = lane >> 2;
    int t = lane & 3;
    float acc[2][8][4];
    #pragma unroll
    for (int i = 0; i < 2; i++)
        #pragma unroll
        for (int j = 0; j < 8; j++)
            #pragma unroll
            for (int q = 0; q < 4; q++) acc[i][j][q] = 0.f;
    int arow = tid & 127;
    int akoff = (tid >> 7) * 16;
    int bkrow = tid >> 3;
    int bnoff = (tid & 7) * 4;
    bool full_n = (col0 + 128 <= Nc);
    const int nchunk = K / BK;
    float4 aR[4]; float4 bR[4];
    {
        const float* ap = A + (size_t)(row0 + arow) * K + akoff;
        #pragma unroll
        for (int u = 0; u < 4; u++) aR[u] = *(const float4*)(ap + 4 * u);
        if (full_n) {
            const float* bp = W + (size_t)bkrow * Nc + col0 + bnoff;
            #pragma unroll
            for (int u = 0; u < 4; u++) bR[u] = *(const float4*)(bp + 32 * u);
        } else {
            #pragma unroll
            for (int u = 0; u < 4; u++) {
                float tmp[4];
                #pragma unroll
                for (int q = 0; q < 4; q++) {
                    int gc = col0 + bnoff + 32 * u + q;
                    tmp[q] = (gc < Nc) ? W[(size_t)bkrow * Nc + gc] : 0.f;
                }
                bR[u] = make_float4(tmp[0], tmp[1], tmp[2], tmp[3]);
            }
        }
    }
    {
        unsigned *Ab = Ab_, *As = As_, *Bb = Bb_, *Bs = Bs_;
        #pragma unroll
        for (int u = 0; u < 4; u++) {
            float v[4] = {aR[u].x, aR[u].y, aR[u].z, aR[u].w};
            #pragma unroll
            for (int q = 0; q < 4; q++) {
                unsigned ub, us; tfsplit(v[q], ub, us);
                Ab[(akoff + 4*u + q) * LDT + arow] = ub;
                As[(akoff + 4*u + q) * LDT + arow] = us;
            }
        }
        #pragma unroll
        for (int u = 0; u < 4; u++) {
            float v[4] = {bR[u].x, bR[u].y, bR[u].z, bR[u].w};
            unsigned ub[4], us[4];
            #pragma unroll
            for (int q = 0; q < 4; q++) tfsplit(v[q], ub[q], us[q]);
            *(uint4*)(Bb + bkrow * LDT + bnoff + 32 * u) = make_uint4(ub[0], ub[1], ub[2], ub[3]);
            *(uint4*)(Bs + bkrow * LDT + bnoff + 32 * u) = make_uint4(us[0], us[1], us[2], us[3]);
        }
    }
    __syncthreads();
    for (int c = 0; c < nchunk; c++) {
        int cur = c & 1;
        if (c + 1 < nchunk) {
            int k0g = (c + 1) * BK;
            const float* ap = A + (size_t)(row0 + arow) * K + k0g + akoff;
            #pragma unroll
            for (int u = 0; u < 4; u++) aR[u] = *(const float4*)(ap + 4 * u);
            if (full_n) {
                const float* bp = W + (size_t)(k0g + bkrow) * Nc + col0 + bnoff;
                #pragma unroll
                for (int u = 0; u < 4; u++) bR[u] = *(const float4*)(bp + 32 * u);
            } else {
                #pragma unroll
                for (int u = 0; u < 4; u++) {
                    float tmp[4];
                    #pragma unroll
                    for (int q = 0; q < 4; q++) {
                        int gc = col0 + bnoff + 32 * u + q;
                        tmp[q] = (gc < Nc) ? W[(size_t)(k0g + bkrow) * Nc + gc] : 0.f;
                    }
                    bR[u] = make_float4(tmp[0], tmp[1], tmp[2], tmp[3]);
                }
            }
        }
        {
            const unsigned* Ab = Ab_ + cur * TSZ;
            const unsigned* As = As_ + cur * TSZ;
            const unsigned* Bb = Bb_ + cur * TSZ;
            const unsigned* Bs = Bs_ + cur * TSZ;
            #pragma unroll
            for (int kk = 0; kk < 4; kk++) {
                int k0 = kk * 8;
                unsigned aFb[2][4], aFs[2][4];
                #pragma unroll
                for (int mt = 0; mt < 2; mt++) {
                    int m0 = wm + mt * 16 + g;
                    int i00 = (k0 + t) * LDT + m0;
                    int i01 = (k0 + t + 4) * LDT + m0;
                    aFb[mt][0] = Ab[i00]; aFb[mt][1] = Ab[i00 + 8];
                    aFb[mt][2] = Ab[i01]; aFb[mt][3] = Ab[i01 + 8];
                    aFs[mt][0] = As[i00]; aFs[mt][1] = As[i00 + 8];
                    aFs[mt][2] = As[i01]; aFs[mt][3] = As[i01 + 8];
                }
                #pragma unroll
                for (int nt = 0; nt < 8; nt++) {
                    int n0 = wn + nt * 8 + g;
                    int j0 = (k0 + t) * LDT + n0;
                    int j1 = (k0 + t + 4) * LDT + n0;
                    unsigned b0b = Bb[j0], b1b = Bb[j1];
                    unsigned b0s = Bs[j0], b1s = Bs[j1];
                    #pragma unroll
                    for (int mt = 0; mt < 2; mt++) {
                        asm volatile(
                            "mma.sync.aligned.m16n8k8.row.col.f32.tf32.tf32.f32 "
                            "{%0,%1,%2,%3}, {%4,%5,%6,%7}, {%8,%9}, {%0,%1,%2,%3};"
                            : "+f"(acc[mt][nt][0]), "+f"(acc[mt][nt][1]),
                              "+f"(acc[mt][nt][2]), "+f"(acc[mt][nt][3])
                            : "r"(aFs[mt][0]), "r"(aFs[mt][1]), "r"(aFs[mt][2]), "r"(aFs[mt][3]),
                              "r"(b0b), "r"(b1b));
                        asm volatile(
                            "mma.sync.aligned.m16n8k8.row.col.f32.tf32.tf32.f32 "
                            "{%0,%1,%2,%3}, {%4,%5,%6,%7}, {%8,%9}, {%0,%1,%2,%3};"
                            : "+f"(acc[mt][nt][0]), "+f"(acc[mt][nt][1]),
                              "+f"(acc[mt][nt][2]), "+f"(acc[mt][nt][3])
                            : "r"(aFb[mt][0]), "r"(aFb[mt][1]), "r"(aFb[mt][2]), "r"(aFb[mt][3]),
                              "r"(b0s), "r"(b1s));
                        asm volatile(
                            "mma.sync.aligned.m16n8k8.row.col.f32.tf32.tf32.f32 "
                            "{%0,%1,%2,%3}, {%4,%5,%6,%7}, {%8,%9}, {%0,%1,%2,%3};"
                            : "+f"(acc[mt][nt][0]), "+f"(acc[mt][nt][1]),
                              "+f"(acc[mt][nt][2]), "+f"(acc[mt][nt][3])
                            : "r"(aFb[mt][0]), "r"(aFb[mt][1]), "r"(aFb[mt][2]), "r"(aFb[mt][3]),
                              "r"(b0b), "r"(b1b));
                    }
                }
            }
        }
        if (c + 1 < nchunk) {
            int nxt = (c + 1) & 1;
            unsigned *Ab = Ab_ + nxt * TSZ, *As = As_ + nxt * TSZ;
            unsigned *Bb = Bb_ + nxt * TSZ, *Bs = Bs_ + nxt * TSZ;
            #pragma unroll
            for (int u = 0; u < 4; u++) {
                float v[4] = {aR[u].x, aR[u].y, aR[u].z, aR[u].w};
                #pragma unroll
                for (int q = 0; q < 4; q++) {
                    unsigned ub, us; tfsplit(v[q], ub, us);
                    Ab[(akoff + 4*u + q) * LDT + arow] = ub;
                    As[(akoff + 4*u + q) * LDT + arow] = us;
                }
            }
            #pragma unroll
            for (int u = 0; u < 4; u++) {
                float v[4] = {bR[u].x, bR[u].y, bR[u].z, bR[u].w};
                unsigned ub[4], us[4];
                #pragma unroll
                for (int q = 0; q < 4; q++) tfsplit(v[q], ub[q], us[q]);
                *(uint4*)(Bb + bkrow * LDT + bnoff + 32 * u) = make_uint4(ub[0], ub[1], ub[2], ub[3]);
                *(uint4*)(Bs + bkrow * LDT + bnoff + 32 * u) = make_uint4(us[0], us[1], us[2], us[3]);
            }
            __syncthreads();
        }
    }
    #pragma unroll
    for (int mt = 0; mt < 2; mt++) {
        #pragma unroll
        for (int half = 0; half < 2; half++) {
            int gr = row0 + wm + mt * 16 + g + half * 8;
            #pragma unroll
            for (int nt = 0; nt < 8; nt++) {
                int gc = col0 + wn + nt * 8 + 2 * t;
                if (gc >= Nc) continue;
                float v0 = acc[mt][nt][half * 2 + 0];
                float v1 = acc[mt][nt][half * 2 + 1];
                if (bias) { v0 += bias[gc]; v1 += bias[gc + 1]; }
                if (mode == 1) {
                    const float2 rv = *(const float2*)(R + (size_t)gr * Nc + gc);
                    v0 += rv.x; v1 += rv.y;
                } else if (mode == 2) {
                    v0 = 0.5f * v0 * (1.f + erff(v0 * 0.70710678118654752f));
                    v1 = 0.5f * v1 * (1.f + erff(v1 * 0.70710678118654752f));
                }
                *(float2*)(C + (size_t)gr * Nc + gc) = make_float2(v0, v1);
            }
        }
    }
}

// ---------------- attention: 2 blocks per (batch,head), query-split, 256 threads ----------------
// Block handles query rows [q0, q0+nq): s=0 -> rows 0..32 (nq=33), s=1 -> rows 33..64 (nq=32).
#define QS_ROWS 33
#define ATTN_SMEM_B ((QS_ROWS*65 + 2*NTOK*65 + QS_ROWS*66) * 4)
__global__ __launch_bounds__(256) void attn_kernel(const float* __restrict__ qkv,
        const float* __restrict__ biasfull, float* __restrict__ o) {
    extern __shared__ float smf[];
    float* qs = smf;                         // [nq][65]
    float* ks = smf + QS_ROWS * 65;          // [65][65]
    float* vs = ks + NTOK * 65;              // [65][65]
    float* sc = vs + NTOK * 65;              // [nq][66]
    int bhs = blockIdx.x;
    int s = bhs & 1;
    int bh = bhs >> 1;
    int b = bh / HEADS, hd = bh % HEADS;
    int q0 = s * 33;
    int nq = s ? 32 : 33;
    int tid = threadIdx.x;
    const float* base = qkv + (size_t)b * NTOK * (3 * INNERD) + hd * DHD;
    // load K, V (full) and Q (this block's rows)
    for (int e = tid; e < NTOK * DHD; e += 256) {
        int i = e >> 6, d = e & 63;
        const float* r = base + (size_t)i * (3 * INNERD);
        ks[i * 65 + d] = r[INNERD + d];
        vs[i * 65 + d] = r[2 * INNERD + d];
    }
    for (int e = tid; e < nq * DHD; e += 256) {
        int i = e >> 6, d = e & 63;
        qs[i * 65 + d] = base[(size_t)(q0 + i) * (3 * INNERD) + d];
    }
    __syncthreads();
    // scores: [nq][65]
    int ntile = (nq + 3) >> 2;   // 9
    for (int t = tid; t < ntile * 17; t += 256) {
        int ti = (t / 17) * 4, tj = (t % 17) * 4;
        float acc[4][4] = {};
        #pragma unroll 8
        for (int kk = 0; kk < DHD; kk++) {
            float a[4], w[4];
            #pragma unroll
            for (int u = 0; u < 4; u++) { int ii = ti + u; if (ii >= nq) ii = nq - 1; a[u] = qs[ii * 65 + kk]; }
            #pragma unroll
            for (int u = 0; u < 4; u++) { int jj = tj + u; if (jj > 64) jj = 64; w[u] = ks[jj * 65 + kk]; }
            #pragma unroll
            for (int i = 0; i < 4; i++)
                #pragma unroll
                for (int j = 0; j < 4; j++) acc[i][j] = fmaf(a[i], w[j], acc[i][j]);
        }
        #pragma unroll
        for (int u = 0; u < 4; u++) {
            int ii = ti + u; if (ii >= nq) break;
            #pragma unroll
            for (int v = 0; v < 4; v++) {
                int jj = tj + v; if (jj > 64) break;
                sc[ii * 66 + jj] = acc[u][v] * 0.125f + biasfull[(q0 + ii) * NTOK + jj];
            }
        }
    }
    __syncthreads();
    // per-row top-16 + softmax (tie-break matches lax.top_k)
    int warp = tid >> 5, lane = tid & 31;
    for (int row = warp; row < nq; row += 8) {
        float v0 = sc[row * 66 + lane];
        float v1 = sc[row * 66 + 32 + lane];
        float v2 = (lane == 0) ? sc[row * 66 + 64] : -3.402823466e38f;
        bool a0 = true, a1 = true, a2 = (lane == 0);
        bool s0 = false, s1 = false, s2 = false;
        float rowmax = 0.f;
        for (int it = 0; it < TOPK; it++) {
            float bv = -3.402823466e38f; int bi = 127;
            if (a0)            { bv = v0; bi = lane; }
            if (a1 && v1 > bv) { bv = v1; bi = lane + 32; }
            if (a2 && v2 > bv) { bv = v2; bi = 64; }
            #pragma unroll
            for (int off = 16; off; off >>= 1) {
                float ov = __shfl_down_sync(0xffffffffu, bv, off);
                int   oi = __shfl_down_sync(0xffffffffu, bi, off);
                if (ov > bv || (ov == bv && oi < bi)) { bv = ov; bi = oi; }
            }
            bv = __shfl_sync(0xffffffffu, bv, 0);
            bi = __shfl_sync(0xffffffffu, bi, 0);
            if (it == 0) rowmax = bv;
            if (bi == lane)              { a0 = false; s0 = true; }
            else if (bi == lane + 32)    { a1 = false; s1 = true; }
            else if (bi == 64 && lane==0){ a2 = false; s2 = true; }
        }
        float e0 = s0 ? expf(v0 - rowmax) : 0.f;
        float e1 = s1 ? expf(v1 - rowmax) : 0.f;
        float e2 = s2 ? expf(v2 - rowmax) : 0.f;
        float sum = e0 + e1 + e2;
        #pragma unroll
        for (int off = 16; off; off >>= 1) sum += __shfl_down_sync(0xffffffffu, sum, off);
        sum = __shfl_sync(0xffffffffu, sum, 0);
        float inv = 1.0f / sum;
        sc[row * 66 + lane] = e0 * inv;
        sc[row * 66 + 32 + lane] = e1 * inv;
        if (lane == 0) sc[row * 66 + 64] = e2 * inv;
    }
    __syncthreads();
    // out = attn @ v, rows [q0, q0+nq)
    for (int t = tid; t < ntile * 16; t += 256) {
        int ti = (t >> 4) << 2, td = (t & 15) << 2;
        float acc[4][4] = {};
        for (int j = 0; j < NTOK; j++) {
            float a[4], w[4];
            #pragma unroll
            for (int u = 0; u < 4; u++) { int ii = ti + u; if (ii >= nq) ii = nq - 1; a[u] = sc[ii * 66 + j]; }
            #pragma unroll
            for (int u = 0; u < 4; u++) w[u] = vs[j * 65 + td + u];
            #pragma unroll
            for (int i2 = 0; i2 < 4; i2++)
                #pragma unroll
                for (int j2 = 0; j2 < 4; j2++) acc[i2][j2] = fmaf(a[i2], w[j2], acc[i2][j2]);
        }
        #pragma unroll
        for (int u = 0; u < 4; u++) {
            int ii = ti + u; if (ii >= nq) break;
            float* orow = o + ((size_t)b * NTOK + q0 + ii) * INNERD + hd * DHD + td;
            #pragma unroll
            for (int v = 0; v < 4; v++) orow[v] = acc[u][v];
        }
    }
}

// ---------------- host orchestration ----------------
extern "C" void kernel_launch(void* const* d_in, const int* in_sizes, int n_in,
                              void* d_out, int out_size) {
    (void)in_sizes; (void)n_in; (void)out_size;
    const float* img       = (const float*)d_in[0];
    const float* pe_ln1_w  = (const float*)d_in[1];
    const float* pe_ln1_b  = (const float*)d_in[2];
    const float* pe_w      = (const float*)d_in[3];
    const float* pe_b      = (const float*)d_in[4];
    const float* pe_ln2_w  = (const float*)d_in[5];
    const float* pe_ln2_b  = (const float*)d_in[6];
    const float* cls_tok   = (const float*)d_in[7];
    const float* pos_emb   = (const float*)d_in[8];
    const float* attn_ln_w = (const float*)d_in[9];
    const float* attn_ln_b = (const float*)d_in[10];
    const float* qkv_w     = (const float*)d_in[11];
    const float* out_w     = (const float*)d_in[12];
    const float* out_b     = (const float*)d_in[13];
    const float* btab      = (const float*)d_in[14];
    const float* ff_ln_w   = (const float*)d_in[15];
    const float* ff_ln_b   = (const float*)d_in[16];
    const float* ff_w1     = (const float*)d_in[17];
    const float* ff_b1     = (const float*)d_in[18];
    const float* ff_w2     = (const float*)d_in[19];
    const float* ff_b2     = (const float*)d_in[20];
    const float* fin_ln_w  = (const float*)d_in[21];
    const float* fin_ln_b  = (const float*)d_in[22];
    const float* head_w    = (const float*)d_in[23];
    const float* head_b    = (const float*)d_in[24];
    float* out = (float*)d_out;

    float *px, *pln, *pmlp, *pqkv, *po, *pbias;
    __half *wb, *ws;
    cudaGetSymbolAddress((void**)&px,   g_x);
    cudaGetSymbolAddress((void**)&pln,  g_ln);
    cudaGetSymbolAddress((void**)&pmlp, g_mlp);
    cudaGetSymbolAddress((void**)&pqkv, g_qkv);
    cudaGetSymbolAddress((void**)&po,   g_o);
    cudaGetSymbolAddress((void**)&pbias,g_bias);
    cudaGetSymbolAddress((void**)&wb,   g_wb);
    cudaGetSymbolAddress((void**)&ws,   g_ws);

    cudaFuncSetAttribute(attn_kernel, cudaFuncAttributeMaxDynamicSharedMemorySize, ATTN_SMEM_B);
    const int GEMM_SMEM = 8 * TSZ * 4;
    cudaFuncSetAttribute(gemm_tc_kernel, cudaFuncAttributeMaxDynamicSharedMemorySize, GEMM_SMEM);
    cudaFuncSetAttribute(gemm_h2_kernel, cudaFuncAttributeMaxDynamicSharedMemorySize, H2_SMEM);

    patch_kernel<<<PROWS, 256>>>(img, pe_ln1_w, pe_ln1_b, pmlp);                       // 0
    tsplit_kernel<<<dim3(384/32, 768/32, 1), 256>>>(pe_w, wb + OFF_PE, ws + OFF_PE,    // 1
                                                    768, 384, 0, 0);
    tsplit_kernel<<<dim3(1152/32, 384/32, 12), 256>>>(qkv_w, wb + OFF_QKV, ws + OFF_QKV, // 2
                                                      384, 1152, (long)384*1152, (long)SZ_QKV);
    gemm_h2_kernel<<<dim3(3, PROWS/128), 256, H2_SMEM>>>(                              // 3
        pmlp, wb + OFF_PE, ws + OFF_PE, pe_b, nullptr, pln, PROWS, EDIM, PDIM, 0);
    tsplit_kernel<<<dim3(384/32, 384/32, 12), 256>>>(out_w, wb + OFF_OUT, ws + OFF_OUT, // 4
                                                     384, 384, (long)384*384, (long)SZ_OUT);
    tsplit_kernel<<<dim3(1536/32, 384/32, 12), 256>>>(ff_w1, wb + OFF_FF1, ws + OFF_FF1, // 5
                                                      384, 1536, (long)384*1536, (long)SZ_FF1);
    tsplit_kernel<<<dim3(384/32, 1536/32, 12), 256>>>(ff_w2, wb + OFF_FF2, ws + OFF_FF2, // 6
                                                      1536, 384, (long)1536*384, (long)SZ_FF2);
    bias_kernel<<<DEPTH, 256>>>(btab, pbias);                                          // 7
    ln_pos_kernel<<<PROWS, 128>>>(pln, pe_ln2_w, pe_ln2_b, pos_emb, px);               // 8
    cls_kernel<<<BATCH, EDIM>>>(cls_tok, pos_emb, px);                                 // 9

    for (int l = 0; l < DEPTH; l++) {
        ln_kernel<<<ROWS, 128>>>(px, EDIM, attn_ln_w + l * EDIM, attn_ln_b + l * EDIM, pln, EDIM);
        gemm_h2_kernel<<<dim3(9, ROWS/128), 256, H2_SMEM>>>(
            pln, wb + OFF_QKV + (size_t)l * SZ_QKV, ws + OFF_QKV + (size_t)l * SZ_QKV,
            nullptr, nullptr, pqkv, ROWS, 1152, EDIM, 0);
        attn_kernel<<<BATCH * HEADS * 2, 256, ATTN_SMEM_B>>>(pqkv, pbias + l * NTOK * NTOK, po);
        gemm_h2_kernel<<<dim3(3, ROWS/128), 256, H2_SMEM>>>(
            po, wb + OFF_OUT + (size_t)l * SZ_OUT, ws + OFF_OUT + (size_t)l * SZ_OUT,
            out_b + l * EDIM, px, px, ROWS, EDIM, EDIM, 1);
        ln_kernel<<<ROWS, 128>>>(px, EDIM, ff_ln_w + l * EDIM, ff_ln_b + l * EDIM, pln, EDIM);
        gemm_h2_kernel<<<dim3(12, ROWS/128), 256, H2_SMEM>>>(
            pln, wb + OFF_FF1 + (size_t)l * SZ_FF1, ws + OFF_FF1 + (size_t)l * SZ_FF1,
            ff_b1 + l * MLPDIM, nullptr, pmlp, ROWS, MLPDIM, EDIM, 2);
        gemm_h2_kernel<<<dim3(3, ROWS/128), 256, H2_SMEM>>>(
            pmlp, wb + OFF_FF2 + (size_t)l * SZ_FF2, ws + OFF_FF2 + (size_t)l * SZ_FF2,
            ff_b2 + l * EDIM, px, px, ROWS, EDIM, MLPDIM, 1);
    }

    ln_kernel<<<BATCH, 128>>>(px, NTOK * EDIM, fin_ln_w, fin_ln_b, pln, EDIM);
    gemm_tc_kernel<<<dim3((NCLS + 127) / 128, BATCH / 128), 256, GEMM_SMEM>>>(
        pln, head_w, head_b, nullptr, out, BATCH, NCLS, EDIM, 0);
}